// round 1
// baseline (speedup 1.0000x reference)
#include <cuda_runtime.h>
#include <cstdint>

#define EMBED 2048
#define NHEAD 16
#define HDIM  128
#define BATCH 2
#define SEQ   2048
#define MROWS (BATCH*SEQ)   // 4096

// Scratch (allocation-free contract: __device__ globals)
__device__ float g_Q[(size_t)BATCH*NHEAD*SEQ*HDIM];
__device__ float g_K[(size_t)BATCH*NHEAD*SEQ*HDIM];
__device__ float g_V[(size_t)BATCH*NHEAD*SEQ*HDIM];
__device__ float g_C[(size_t)MROWS*EMBED];

__device__ __forceinline__ float to_tf32(float x) {
    uint32_t u;
    asm("cvt.rna.tf32.f32 %0, %1;" : "=r"(u) : "f"(x));
    return __uint_as_float(u);
}

__device__ __forceinline__ void mma_tf32(float c[4], const float a[4], float b0, float b1) {
    asm("mma.sync.aligned.m16n8k8.row.col.f32.tf32.tf32.f32 "
        "{%0,%1,%2,%3}, {%4,%5,%6,%7}, {%8,%9}, {%0,%1,%2,%3};"
        : "+f"(c[0]), "+f"(c[1]), "+f"(c[2]), "+f"(c[3])
        : "r"(__float_as_uint(a[0])), "r"(__float_as_uint(a[1])),
          "r"(__float_as_uint(a[2])), "r"(__float_as_uint(a[3])),
          "r"(__float_as_uint(b0)),  "r"(__float_as_uint(b1)));
}

// ---------------------------------------------------------------------------
// TF32 GEMM: C[M,N] = A[M,K] @ W[N,K]^T + bias
// M=4096, N=2048, K=2048. Block 128x128, K-tile 32, 8 warps (warp tile 64x32).
// mode 0: C row-major [M,N]. mode 1: scatter to [B,H,S,D] (qkv layout).
// ---------------------------------------------------------------------------
__global__ void __launch_bounds__(256) gemm_tf32_kernel(
    const float* __restrict__ A, const float* __restrict__ W,
    const float* __restrict__ bias, float* __restrict__ C, int mode)
{
    const int M = MROWS, N = EMBED, K = EMBED;
    __shared__ float As[128][36];   // [m][k], stride 36 -> conflict-free ld/st
    __shared__ float Bs[128][36];   // [n][k]

    int tid  = threadIdx.x;
    int lane = tid & 31, wid = tid >> 5;
    int tig  = lane & 3, grp = lane >> 2;
    int wm   = (wid >> 2) * 64;     // warp row offset (2 rows of warps)
    int wn   = (wid & 3) * 32;      // warp col offset (4 cols of warps)
    int bm   = blockIdx.y * 128, bn = blockIdx.x * 128;

    float acc[4][4][4];
#pragma unroll
    for (int i = 0; i < 4; i++)
#pragma unroll
        for (int j = 0; j < 4; j++)
#pragma unroll
            for (int r = 0; r < 4; r++) acc[i][j][r] = 0.f;

    for (int kt = 0; kt < K; kt += 32) {
        // Load 128x32 tiles of A and W (coalesced float4), convert to tf32.
#pragma unroll
        for (int p = 0; p < 4; p++) {
            int f  = tid + p * 256;          // 1024 float4 per tile
            int r  = f >> 3;
            int c4 = (f & 7) << 2;
            float4 va = *(const float4*)(A + (size_t)(bm + r) * K + kt + c4);
            As[r][c4+0] = to_tf32(va.x); As[r][c4+1] = to_tf32(va.y);
            As[r][c4+2] = to_tf32(va.z); As[r][c4+3] = to_tf32(va.w);
            float4 vb = *(const float4*)(W + (size_t)(bn + r) * K + kt + c4);
            Bs[r][c4+0] = to_tf32(vb.x); Bs[r][c4+1] = to_tf32(vb.y);
            Bs[r][c4+2] = to_tf32(vb.z); Bs[r][c4+3] = to_tf32(vb.w);
        }
        __syncthreads();

#pragma unroll
        for (int ks = 0; ks < 4; ks++) {
            int k0 = ks * 8;
            float a[4][4], bb[4][2];
#pragma unroll
            for (int mi = 0; mi < 4; mi++) {
                int m0 = wm + mi * 16;
                a[mi][0] = As[m0 + grp    ][k0 + tig    ];
                a[mi][1] = As[m0 + grp + 8][k0 + tig    ];
                a[mi][2] = As[m0 + grp    ][k0 + tig + 4];
                a[mi][3] = As[m0 + grp + 8][k0 + tig + 4];
            }
#pragma unroll
            for (int ni = 0; ni < 4; ni++) {
                int n0 = wn + ni * 8;
                bb[ni][0] = Bs[n0 + grp][k0 + tig    ];
                bb[ni][1] = Bs[n0 + grp][k0 + tig + 4];
            }
#pragma unroll
            for (int mi = 0; mi < 4; mi++)
#pragma unroll
                for (int ni = 0; ni < 4; ni++)
                    mma_tf32(acc[mi][ni], a[mi], bb[ni][0], bb[ni][1]);
        }
        __syncthreads();
    }

    // Epilogue: add bias, write out.
#pragma unroll
    for (int mi = 0; mi < 4; mi++) {
#pragma unroll
        for (int ni = 0; ni < 4; ni++) {
            int m0 = bm + wm + mi * 16 + grp;
            int n0 = bn + wn + ni * 8 + tig * 2;
            float bv0 = bias[n0], bv1 = bias[n0 + 1];
            float v00 = acc[mi][ni][0] + bv0, v01 = acc[mi][ni][1] + bv1;
            float v10 = acc[mi][ni][2] + bv0, v11 = acc[mi][ni][3] + bv1;
            if (mode == 0) {
                C[(size_t)m0 * N + n0]       = v00;
                C[(size_t)m0 * N + n0 + 1]   = v01;
                C[(size_t)(m0+8) * N + n0]   = v10;
                C[(size_t)(m0+8) * N + n0+1] = v11;
            } else {
                // [B,H,S,D]: ((b*H + h)*S + s)*D + d ; b=m>>11, s=m&2047, h=n>>7, d=n&127
                size_t i0 = ((size_t)((m0 >> 11) * NHEAD + (n0 >> 7))) * (SEQ * HDIM)
                          + (size_t)(m0 & (SEQ-1)) * HDIM + (n0 & (HDIM-1));
                size_t i1 = ((size_t)(((m0+8) >> 11) * NHEAD + (n0 >> 7))) * (SEQ * HDIM)
                          + (size_t)((m0+8) & (SEQ-1)) * HDIM + (n0 & (HDIM-1));
                C[i0] = v00; C[i0 + 1] = v01;
                C[i1] = v10; C[i1 + 1] = v11;
            }
        }
    }
}

// ---------------------------------------------------------------------------
// Causal flash attention. Block = 128 q-rows of one (b,h). 8 warps, each owns
// 16 q-rows. Key tiles of 64. TF32 mma for QK^T and PV, fp32 online softmax.
// ---------------------------------------------------------------------------
#define SQ 132   // stride for 128-wide fp32 tiles (conflict-free)
#define SP 68    // stride for 64-wide P tile

#define QS_ELEMS (128*SQ)
#define KS_ELEMS (64*SQ)
#define VS_ELEMS (64*SQ)
#define PS_ELEMS (128*SP)
#define ATTN_SMEM ((QS_ELEMS + KS_ELEMS + VS_ELEMS + PS_ELEMS) * 4)

__global__ void __launch_bounds__(256) attn_kernel(
    const float* __restrict__ Q, const float* __restrict__ K,
    const float* __restrict__ V, float* __restrict__ Ctx)
{
    extern __shared__ float sm[];
    float* Qs = sm;                          // [128][SQ]
    float* Ks = Qs + QS_ELEMS;               // [64][SQ]
    float* Vs = Ks + KS_ELEMS;               // [64][SQ]
    float* Ps = Vs + VS_ELEMS;               // [128][SP]

    int tid  = threadIdx.x;
    int lane = tid & 31, wid = tid >> 5;
    int tig  = lane & 3, grp = lane >> 2;
    int bh   = blockIdx.y;
    int qt   = gridDim.x - 1 - blockIdx.x;   // big-work blocks first
    int q0   = qt * 128;
    int wrow = wid * 16;

    const size_t off = (size_t)bh * SEQ * HDIM;
    const float* Qp = Q + off + (size_t)q0 * HDIM;
    const float* Kp = K + off;
    const float* Vp = V + off;
    const float scale = 0.08838834764831845f;  // 1/sqrt(128)

    // Load Q tile (128x128), pre-scaled + tf32.
#pragma unroll
    for (int p = 0; p < 16; p++) {
        int f  = tid + p * 256;  // 4096 float4
        int r  = f >> 5;
        int c4 = (f & 31) << 2;
        float4 v = *(const float4*)(Qp + (size_t)r * HDIM + c4);
        Qs[r*SQ + c4+0] = to_tf32(v.x * scale);
        Qs[r*SQ + c4+1] = to_tf32(v.y * scale);
        Qs[r*SQ + c4+2] = to_tf32(v.z * scale);
        Qs[r*SQ + c4+3] = to_tf32(v.w * scale);
    }

    float o[16][4];
#pragma unroll
    for (int i = 0; i < 16; i++)
#pragma unroll
        for (int r = 0; r < 4; r++) o[i][r] = 0.f;
    float m_lo = -1e30f, m_hi = -1e30f, l_lo = 0.f, l_hi = 0.f;

    int row_lo = q0 + wrow + grp;
    int row_hi = row_lo + 8;
    int nkt = 2 * qt + 2;   // key tiles intersecting the causal region

    for (int kt = 0; kt < nkt; kt++) {
        __syncthreads();
        // Load K,V tiles (64x128 each).
#pragma unroll
        for (int p = 0; p < 8; p++) {
            int f  = tid + p * 256;  // 2048 float4
            int r  = f >> 5;
            int c4 = (f & 31) << 2;
            const float* kp = Kp + (size_t)(kt * 64 + r) * HDIM + c4;
            const float* vp = Vp + (size_t)(kt * 64 + r) * HDIM + c4;
            float4 vk = *(const float4*)kp;
            Ks[r*SQ + c4+0] = to_tf32(vk.x); Ks[r*SQ + c4+1] = to_tf32(vk.y);
            Ks[r*SQ + c4+2] = to_tf32(vk.z); Ks[r*SQ + c4+3] = to_tf32(vk.w);
            float4 vv = *(const float4*)vp;
            Vs[r*SQ + c4+0] = to_tf32(vv.x); Vs[r*SQ + c4+1] = to_tf32(vv.y);
            Vs[r*SQ + c4+2] = to_tf32(vv.z); Vs[r*SQ + c4+3] = to_tf32(vv.w);
        }
        __syncthreads();

        // S = Q @ K^T : warp computes 16x64.
        float s[8][4];
#pragma unroll
        for (int i = 0; i < 8; i++)
#pragma unroll
            for (int r = 0; r < 4; r++) s[i][r] = 0.f;
#pragma unroll
        for (int ks = 0; ks < 16; ks++) {
            int k0 = ks * 8;
            float a[4];
            a[0] = Qs[(wrow + grp    )*SQ + k0 + tig    ];
            a[1] = Qs[(wrow + grp + 8)*SQ + k0 + tig    ];
            a[2] = Qs[(wrow + grp    )*SQ + k0 + tig + 4];
            a[3] = Qs[(wrow + grp + 8)*SQ + k0 + tig + 4];
#pragma unroll
            for (int ni = 0; ni < 8; ni++) {
                float b0 = Ks[(ni*8 + grp)*SQ + k0 + tig    ];
                float b1 = Ks[(ni*8 + grp)*SQ + k0 + tig + 4];
                mma_tf32(s[ni], a, b0, b1);
            }
        }

        // Causal mask.
        int colbase = kt * 64 + tig * 2;
#pragma unroll
        for (int ni = 0; ni < 8; ni++) {
            int c0 = colbase + ni * 8, c1 = c0 + 1;
            if (c0 > row_lo) s[ni][0] = -1e9f;
            if (c1 > row_lo) s[ni][1] = -1e9f;
            if (c0 > row_hi) s[ni][2] = -1e9f;
            if (c1 > row_hi) s[ni][3] = -1e9f;
        }

        // Online softmax (per row-half; quad lanes share a row).
        float tmax_lo = -1e30f, tmax_hi = -1e30f;
#pragma unroll
        for (int ni = 0; ni < 8; ni++) {
            tmax_lo = fmaxf(tmax_lo, fmaxf(s[ni][0], s[ni][1]));
            tmax_hi = fmaxf(tmax_hi, fmaxf(s[ni][2], s[ni][3]));
        }
#pragma unroll
        for (int o2 = 1; o2 < 4; o2 <<= 1) {
            tmax_lo = fmaxf(tmax_lo, __shfl_xor_sync(0xffffffffu, tmax_lo, o2));
            tmax_hi = fmaxf(tmax_hi, __shfl_xor_sync(0xffffffffu, tmax_hi, o2));
        }
        float mn_lo = fmaxf(m_lo, tmax_lo), mn_hi = fmaxf(m_hi, tmax_hi);
        float al = __expf(m_lo - mn_lo), ah = __expf(m_hi - mn_hi);
        m_lo = mn_lo; m_hi = mn_hi;

        float sum_lo = 0.f, sum_hi = 0.f;
#pragma unroll
        for (int ni = 0; ni < 8; ni++) {
            float p00 = __expf(s[ni][0] - m_lo);
            float p01 = __expf(s[ni][1] - m_lo);
            float p10 = __expf(s[ni][2] - m_hi);
            float p11 = __expf(s[ni][3] - m_hi);
            sum_lo += p00 + p01;
            sum_hi += p10 + p11;
            int c = ni * 8 + tig * 2;
            Ps[(wrow + grp    )*SP + c    ] = to_tf32(p00);
            Ps[(wrow + grp    )*SP + c + 1] = to_tf32(p01);
            Ps[(wrow + grp + 8)*SP + c    ] = to_tf32(p10);
            Ps[(wrow + grp + 8)*SP + c + 1] = to_tf32(p11);
        }
#pragma unroll
        for (int o2 = 1; o2 < 4; o2 <<= 1) {
            sum_lo += __shfl_xor_sync(0xffffffffu, sum_lo, o2);
            sum_hi += __shfl_xor_sync(0xffffffffu, sum_hi, o2);
        }
        l_lo = l_lo * al + sum_lo;
        l_hi = l_hi * ah + sum_hi;
#pragma unroll
        for (int ni = 0; ni < 16; ni++) {
            o[ni][0] *= al; o[ni][1] *= al;
            o[ni][2] *= ah; o[ni][3] *= ah;
        }
        __syncwarp();

        // O += P @ V : warp 16x128, k=64.
#pragma unroll
        for (int ks = 0; ks < 8; ks++) {
            int k0 = ks * 8;
            float a[4];
            a[0] = Ps[(wrow + grp    )*SP + k0 + tig    ];
            a[1] = Ps[(wrow + grp + 8)*SP + k0 + tig    ];
            a[2] = Ps[(wrow + grp    )*SP + k0 + tig + 4];
            a[3] = Ps[(wrow + grp + 8)*SP + k0 + tig + 4];
#pragma unroll
            for (int ni = 0; ni < 16; ni++) {
                float b0 = Vs[(k0 + tig    )*SQ + ni*8 + grp];
                float b1 = Vs[(k0 + tig + 4)*SQ + ni*8 + grp];
                mma_tf32(o[ni], a, b0, b1);
            }
        }
    }

    // Epilogue: normalize, write to ctx in [B,S,E] layout.
    int b = bh >> 4, h = bh & 15;
    size_t base_lo = ((size_t)b * SEQ + row_lo) * EMBED + h * HDIM;
    size_t base_hi = base_lo + (size_t)8 * EMBED;
    float il_lo = 1.f / l_lo, il_hi = 1.f / l_hi;
#pragma unroll
    for (int ni = 0; ni < 16; ni++) {
        int c = ni * 8 + tig * 2;
        Ctx[base_lo + c]     = o[ni][0] * il_lo;
        Ctx[base_lo + c + 1] = o[ni][1] * il_lo;
        Ctx[base_hi + c]     = o[ni][2] * il_hi;
        Ctx[base_hi + c + 1] = o[ni][3] * il_hi;
    }
}

// ---------------------------------------------------------------------------
extern "C" void kernel_launch(void* const* d_in, const int* in_sizes, int n_in,
                              void* d_out, int out_size) {
    const float* x  = (const float*)d_in[0];
    const float* Wq = (const float*)d_in[1];
    const float* bq = (const float*)d_in[2];
    const float* Wk = (const float*)d_in[3];
    const float* bk = (const float*)d_in[4];
    const float* Wv = (const float*)d_in[5];
    const float* bv = (const float*)d_in[6];
    const float* Wo = (const float*)d_in[7];
    const float* bo = (const float*)d_in[8];
    float* out = (float*)d_out;

    float *Qb, *Kb, *Vb, *Cb;
    cudaGetSymbolAddress((void**)&Qb, g_Q);
    cudaGetSymbolAddress((void**)&Kb, g_K);
    cudaGetSymbolAddress((void**)&Vb, g_V);
    cudaGetSymbolAddress((void**)&Cb, g_C);

    dim3 gg(EMBED / 128, MROWS / 128);  // (16, 32)
    gemm_tf32_kernel<<<gg, 256>>>(x, Wq, bq, Qb, 1);
    gemm_tf32_kernel<<<gg, 256>>>(x, Wk, bk, Kb, 1);
    gemm_tf32_kernel<<<gg, 256>>>(x, Wv, bv, Vb, 1);

    cudaFuncSetAttribute(attn_kernel,
                         cudaFuncAttributeMaxDynamicSharedMemorySize, ATTN_SMEM);
    attn_kernel<<<dim3(SEQ / 128, BATCH * NHEAD), 256, ATTN_SMEM>>>(Qb, Kb, Vb, Cb);

    gemm_tf32_kernel<<<gg, 256>>>(Cb, Wo, bo, out, 0);
}

// round 4
// speedup vs baseline: 1.1317x; 1.1317x over previous
#include <cuda_runtime.h>
#include <cstdint>

#define EMBED 2048
#define NHEAD 16
#define HDIM  128
#define BATCH 2
#define SEQ   2048
#define MROWS (BATCH*SEQ)   // 4096

// Scratch (allocation-free contract: __device__ globals)
__device__ float g_Q[(size_t)BATCH*NHEAD*SEQ*HDIM];
__device__ float g_K[(size_t)BATCH*NHEAD*SEQ*HDIM];
__device__ float g_V[(size_t)BATCH*NHEAD*SEQ*HDIM];
__device__ float g_C[(size_t)MROWS*EMBED];

__device__ __forceinline__ float to_tf32(float x) {
    uint32_t u;
    asm("cvt.rna.tf32.f32 %0, %1;" : "=r"(u) : "f"(x));
    return __uint_as_float(u);
}

__device__ __forceinline__ void mma_tf32(float c[4], const float a[4], float b0, float b1) {
    asm("mma.sync.aligned.m16n8k8.row.col.f32.tf32.tf32.f32 "
        "{%0,%1,%2,%3}, {%4,%5,%6,%7}, {%8,%9}, {%0,%1,%2,%3};"
        : "+f"(c[0]), "+f"(c[1]), "+f"(c[2]), "+f"(c[3])
        : "r"(__float_as_uint(a[0])), "r"(__float_as_uint(a[1])),
          "r"(__float_as_uint(a[2])), "r"(__float_as_uint(a[3])),
          "r"(__float_as_uint(b0)),  "r"(__float_as_uint(b1)));
}

// ---------------------------------------------------------------------------
// TF32 GEMM (unchanged from R1 — measured ~91% of legacy tf32 mma peak):
// C[M,N] = A[M,K] @ W[N,K]^T + bias ; block 128x128, K-tile 32, 8 warps.
// mode 0: C row-major [M,N]. mode 1: scatter to [B,H,S,D].
// ---------------------------------------------------------------------------
__global__ void __launch_bounds__(256) gemm_tf32_kernel(
    const float* __restrict__ A, const float* __restrict__ W,
    const float* __restrict__ bias, float* __restrict__ C, int mode)
{
    const int M = MROWS, N = EMBED, K = EMBED;
    __shared__ float As[128][36];
    __shared__ float Bs[128][36];

    int tid  = threadIdx.x;
    int lane = tid & 31, wid = tid >> 5;
    int tig  = lane & 3, grp = lane >> 2;
    int wm   = (wid >> 2) * 64;
    int wn   = (wid & 3) * 32;
    int bm   = blockIdx.y * 128, bn = blockIdx.x * 128;

    float acc[4][4][4];
#pragma unroll
    for (int i = 0; i < 4; i++)
#pragma unroll
        for (int j = 0; j < 4; j++)
#pragma unroll
            for (int r = 0; r < 4; r++) acc[i][j][r] = 0.f;

    for (int kt = 0; kt < K; kt += 32) {
#pragma unroll
        for (int p = 0; p < 4; p++) {
            int f  = tid + p * 256;
            int r  = f >> 3;
            int c4 = (f & 7) << 2;
            float4 va = *(const float4*)(A + (size_t)(bm + r) * K + kt + c4);
            As[r][c4+0] = to_tf32(va.x); As[r][c4+1] = to_tf32(va.y);
            As[r][c4+2] = to_tf32(va.z); As[r][c4+3] = to_tf32(va.w);
            float4 vb = *(const float4*)(W + (size_t)(bn + r) * K + kt + c4);
            Bs[r][c4+0] = to_tf32(vb.x); Bs[r][c4+1] = to_tf32(vb.y);
            Bs[r][c4+2] = to_tf32(vb.z); Bs[r][c4+3] = to_tf32(vb.w);
        }
        __syncthreads();

#pragma unroll
        for (int ks = 0; ks < 4; ks++) {
            int k0 = ks * 8;
            float a[4][4], bb[4][2];
#pragma unroll
            for (int mi = 0; mi < 4; mi++) {
                int m0 = wm + mi * 16;
                a[mi][0] = As[m0 + grp    ][k0 + tig    ];
                a[mi][1] = As[m0 + grp + 8][k0 + tig    ];
                a[mi][2] = As[m0 + grp    ][k0 + tig + 4];
                a[mi][3] = As[m0 + grp + 8][k0 + tig + 4];
            }
#pragma unroll
            for (int ni = 0; ni < 4; ni++) {
                int n0 = wn + ni * 8;
                bb[ni][0] = Bs[n0 + grp][k0 + tig    ];
                bb[ni][1] = Bs[n0 + grp][k0 + tig + 4];
            }
#pragma unroll
            for (int mi = 0; mi < 4; mi++)
#pragma unroll
                for (int ni = 0; ni < 4; ni++)
                    mma_tf32(acc[mi][ni], a[mi], bb[ni][0], bb[ni][1]);
        }
        __syncthreads();
    }

#pragma unroll
    for (int mi = 0; mi < 4; mi++) {
#pragma unroll
        for (int ni = 0; ni < 4; ni++) {
            int m0 = bm + wm + mi * 16 + grp;
            int n0 = bn + wn + ni * 8 + tig * 2;
            float bv0 = bias[n0], bv1 = bias[n0 + 1];
            float v00 = acc[mi][ni][0] + bv0, v01 = acc[mi][ni][1] + bv1;
            float v10 = acc[mi][ni][2] + bv0, v11 = acc[mi][ni][3] + bv1;
            if (mode == 0) {
                C[(size_t)m0 * N + n0]       = v00;
                C[(size_t)m0 * N + n0 + 1]   = v01;
                C[(size_t)(m0+8) * N + n0]   = v10;
                C[(size_t)(m0+8) * N + n0+1] = v11;
            } else {
                size_t i0 = ((size_t)((m0 >> 11) * NHEAD + (n0 >> 7))) * (SEQ * HDIM)
                          + (size_t)(m0 & (SEQ-1)) * HDIM + (n0 & (HDIM-1));
                size_t i1 = ((size_t)(((m0+8) >> 11) * NHEAD + (n0 >> 7))) * (SEQ * HDIM)
                          + (size_t)((m0+8) & (SEQ-1)) * HDIM + (n0 & (HDIM-1));
                C[i0] = v00; C[i0 + 1] = v01;
                C[i1] = v10; C[i1 + 1] = v11;
            }
        }
    }
}

// ---------------------------------------------------------------------------
// Causal flash attention v2 (R3 design, K/V load bug fixed: 16 iters not 8).
// 64 q-rows per CTA, 128 threads (4 warps x 16 rows), 64-key tiles.
// - smem 100KB/CTA -> 2 CTAs/SM (cross-CTA load/compute overlap)
// - Q fragments hoisted to registers (loaded once)
// - P passed S->PV via intra-quad shuffles (no smem round trip)
// - Ks stride 132 / Vs stride 136: all fragment LDS conflict-free
// ---------------------------------------------------------------------------
#define SQK 132
#define SV  136
#define QS_ELEMS (64*SQK)
#define KS_ELEMS (64*SQK)
#define VS_ELEMS (64*SV)
#define ATTN_SMEM ((QS_ELEMS + KS_ELEMS + VS_ELEMS) * 4)   // 102,400 B

__global__ void __launch_bounds__(128, 2) attn_kernel(
    const float* __restrict__ Q, const float* __restrict__ K,
    const float* __restrict__ V, float* __restrict__ Ctx)
{
    extern __shared__ float sm[];
    float* Qs = sm;                // [64][SQK]
    float* Ks = Qs + QS_ELEMS;     // [64][SQK]
    float* Vs = Ks + KS_ELEMS;     // [64][SV]

    int tid  = threadIdx.x;
    int lane = tid & 31, wid = tid >> 5;          // 4 warps
    int tig  = lane & 3, grp = lane >> 2;
    int bh   = blockIdx.y;
    int qt   = gridDim.x - 1 - blockIdx.x;        // big-work blocks first
    int q0   = qt * 64;
    int wrow = wid * 16;

    const size_t off = (size_t)bh * SEQ * HDIM;
    const float* Qp = Q + off + (size_t)q0 * HDIM;
    const float* Kp = K + off;
    const float* Vp = V + off;
    const float scale = 0.08838834764831845f;     // 1/sqrt(128)

    // Load Q tile (64x128 = 2048 float4), pre-scaled + tf32-rounded.
#pragma unroll
    for (int p = 0; p < 16; p++) {
        int f  = tid + p * 128;
        int r  = f >> 5;
        int c4 = (f & 31) << 2;
        float4 v = *(const float4*)(Qp + (size_t)r * HDIM + c4);
        Qs[r*SQK + c4+0] = to_tf32(v.x * scale);
        Qs[r*SQK + c4+1] = to_tf32(v.y * scale);
        Qs[r*SQK + c4+2] = to_tf32(v.z * scale);
        Qs[r*SQK + c4+3] = to_tf32(v.w * scale);
    }
    __syncthreads();

    // Hoist Q fragments for all 16 k-chunks into registers.
    float qf[16][4];
#pragma unroll
    for (int ks = 0; ks < 16; ks++) {
        int k0 = ks * 8;
        qf[ks][0] = Qs[(wrow + grp    )*SQK + k0 + tig    ];
        qf[ks][1] = Qs[(wrow + grp + 8)*SQK + k0 + tig    ];
        qf[ks][2] = Qs[(wrow + grp    )*SQK + k0 + tig + 4];
        qf[ks][3] = Qs[(wrow + grp + 8)*SQK + k0 + tig + 4];
    }

    float o[16][4];
#pragma unroll
    for (int i = 0; i < 16; i++)
#pragma unroll
        for (int r = 0; r < 4; r++) o[i][r] = 0.f;
    float m_lo = -1e30f, m_hi = -1e30f, l_lo = 0.f, l_hi = 0.f;

    int row_lo = q0 + wrow + grp;
    int row_hi = row_lo + 8;
    int src0 = (lane & ~3) + (tig >> 1);   // quad-shuffle sources for P
    int src1 = src0 + 2;
    bool odd = (tig & 1) != 0;

    for (int kt = 0; kt <= qt; kt++) {
        __syncthreads();
        // Load K,V tiles (64x128 = 2048 float4 EACH), tf32-rounded.
#pragma unroll
        for (int p = 0; p < 16; p++) {
            int f  = tid + p * 128;
            int r  = f >> 5;
            int c4 = (f & 31) << 2;
            const float* kp = Kp + (size_t)(kt * 64 + r) * HDIM + c4;
            const float* vp = Vp + (size_t)(kt * 64 + r) * HDIM + c4;
            float4 vk = *(const float4*)kp;
            Ks[r*SQK + c4+0] = to_tf32(vk.x); Ks[r*SQK + c4+1] = to_tf32(vk.y);
            Ks[r*SQK + c4+2] = to_tf32(vk.z); Ks[r*SQK + c4+3] = to_tf32(vk.w);
            float4 vv = *(const float4*)vp;
            Vs[r*SV + c4+0] = to_tf32(vv.x); Vs[r*SV + c4+1] = to_tf32(vv.y);
            Vs[r*SV + c4+2] = to_tf32(vv.z); Vs[r*SV + c4+3] = to_tf32(vv.w);
        }
        __syncthreads();

        // S = Q @ K^T : warp computes 16x64.
        float s[8][4];
#pragma unroll
        for (int i = 0; i < 8; i++)
#pragma unroll
            for (int r = 0; r < 4; r++) s[i][r] = 0.f;
#pragma unroll
        for (int ks = 0; ks < 16; ks++) {
            int k0 = ks * 8;
#pragma unroll
            for (int ni = 0; ni < 8; ni++) {
                float b0 = Ks[(ni*8 + grp)*SQK + k0 + tig    ];
                float b1 = Ks[(ni*8 + grp)*SQK + k0 + tig + 4];
                mma_tf32(s[ni], qf[ks], b0, b1);
            }
        }

        // Causal mask (diagonal tile only; earlier tiles are causally full).
        if (kt == qt) {
            int colbase = kt * 64 + tig * 2;
#pragma unroll
            for (int ni = 0; ni < 8; ni++) {
                int c0 = colbase + ni * 8, c1 = c0 + 1;
                if (c0 > row_lo) s[ni][0] = -1e9f;
                if (c1 > row_lo) s[ni][1] = -1e9f;
                if (c0 > row_hi) s[ni][2] = -1e9f;
                if (c1 > row_hi) s[ni][3] = -1e9f;
            }
        }

        // Online softmax (per row-half; quad lanes share a row).
        float tmax_lo = -1e30f, tmax_hi = -1e30f;
#pragma unroll
        for (int ni = 0; ni < 8; ni++) {
            tmax_lo = fmaxf(tmax_lo, fmaxf(s[ni][0], s[ni][1]));
            tmax_hi = fmaxf(tmax_hi, fmaxf(s[ni][2], s[ni][3]));
        }
#pragma unroll
        for (int o2 = 1; o2 < 4; o2 <<= 1) {
            tmax_lo = fmaxf(tmax_lo, __shfl_xor_sync(0xffffffffu, tmax_lo, o2));
            tmax_hi = fmaxf(tmax_hi, __shfl_xor_sync(0xffffffffu, tmax_hi, o2));
        }
        float mn_lo = fmaxf(m_lo, tmax_lo), mn_hi = fmaxf(m_hi, tmax_hi);
        float al = __expf(m_lo - mn_lo), ah = __expf(m_hi - mn_hi);
        m_lo = mn_lo; m_hi = mn_hi;

        float sum_lo = 0.f, sum_hi = 0.f;
#pragma unroll
        for (int ni = 0; ni < 8; ni++) {
            s[ni][0] = __expf(s[ni][0] - m_lo);
            s[ni][1] = __expf(s[ni][1] - m_lo);
            s[ni][2] = __expf(s[ni][2] - m_hi);
            s[ni][3] = __expf(s[ni][3] - m_hi);
            sum_lo += s[ni][0] + s[ni][1];
            sum_hi += s[ni][2] + s[ni][3];
        }
#pragma unroll
        for (int o2 = 1; o2 < 4; o2 <<= 1) {
            sum_lo += __shfl_xor_sync(0xffffffffu, sum_lo, o2);
            sum_hi += __shfl_xor_sync(0xffffffffu, sum_hi, o2);
        }
        l_lo = l_lo * al + sum_lo;
        l_hi = l_hi * ah + sum_hi;
#pragma unroll
        for (int ni = 0; ni < 16; ni++) {
            o[ni][0] *= al; o[ni][1] *= al;
            o[ni][2] *= ah; o[ni][3] *= ah;
        }

        // O += P @ V. Build P a-fragments from s via intra-quad shuffles:
        // C-frag cols (2*tig, 2*tig+1) -> A-frag cols (tig, tig+4).
#pragma unroll
        for (int ks2 = 0; ks2 < 8; ks2++) {
            float v00 = __shfl_sync(0xffffffffu, s[ks2][0], src0);
            float v01 = __shfl_sync(0xffffffffu, s[ks2][1], src0);
            float v10 = __shfl_sync(0xffffffffu, s[ks2][2], src0);
            float v11 = __shfl_sync(0xffffffffu, s[ks2][3], src0);
            float v20 = __shfl_sync(0xffffffffu, s[ks2][0], src1);
            float v21 = __shfl_sync(0xffffffffu, s[ks2][1], src1);
            float v30 = __shfl_sync(0xffffffffu, s[ks2][2], src1);
            float v31 = __shfl_sync(0xffffffffu, s[ks2][3], src1);
            float a[4];
            a[0] = to_tf32(odd ? v01 : v00);
            a[1] = to_tf32(odd ? v11 : v10);
            a[2] = to_tf32(odd ? v21 : v20);
            a[3] = to_tf32(odd ? v31 : v30);
            int k0 = ks2 * 8;
#pragma unroll
            for (int ni = 0; ni < 16; ni++) {
                float b0 = Vs[(k0 + tig    )*SV + ni*8 + grp];
                float b1 = Vs[(k0 + tig + 4)*SV + ni*8 + grp];
                mma_tf32(o[ni], a, b0, b1);
            }
        }
    }

    // Epilogue: normalize, write ctx [B,S,E].
    int b = bh >> 4, h = bh & 15;
    size_t base_lo = ((size_t)b * SEQ + row_lo) * EMBED + h * HDIM;
    size_t base_hi = base_lo + (size_t)8 * EMBED;
    float il_lo = 1.f / l_lo, il_hi = 1.f / l_hi;
#pragma unroll
    for (int ni = 0; ni < 16; ni++) {
        int c = ni * 8 + tig * 2;
        Ctx[base_lo + c]     = o[ni][0] * il_lo;
        Ctx[base_lo + c + 1] = o[ni][1] * il_lo;
        Ctx[base_hi + c]     = o[ni][2] * il_hi;
        Ctx[base_hi + c + 1] = o[ni][3] * il_hi;
    }
}

// ---------------------------------------------------------------------------
extern "C" void kernel_launch(void* const* d_in, const int* in_sizes, int n_in,
                              void* d_out, int out_size) {
    const float* x  = (const float*)d_in[0];
    const float* Wq = (const float*)d_in[1];
    const float* bq = (const float*)d_in[2];
    const float* Wk = (const float*)d_in[3];
    const float* bk = (const float*)d_in[4];
    const float* Wv = (const float*)d_in[5];
    const float* bv = (const float*)d_in[6];
    const float* Wo = (const float*)d_in[7];
    const float* bo = (const float*)d_in[8];
    float* out = (float*)d_out;

    float *Qb, *Kb, *Vb, *Cb;
    cudaGetSymbolAddress((void**)&Qb, g_Q);
    cudaGetSymbolAddress((void**)&Kb, g_K);
    cudaGetSymbolAddress((void**)&Vb, g_V);
    cudaGetSymbolAddress((void**)&Cb, g_C);

    dim3 gg(EMBED / 128, MROWS / 128);  // (16, 32)
    gemm_tf32_kernel<<<gg, 256>>>(x, Wq, bq, Qb, 1);
    gemm_tf32_kernel<<<gg, 256>>>(x, Wk, bk, Kb, 1);
    gemm_tf32_kernel<<<gg, 256>>>(x, Wv, bv, Vb, 1);

    cudaFuncSetAttribute(attn_kernel,
                         cudaFuncAttributeMaxDynamicSharedMemorySize, ATTN_SMEM);
    attn_kernel<<<dim3(SEQ / 64, BATCH * NHEAD), 128, ATTN_SMEM>>>(Qb, Kb, Vb, Cb);

    gemm_tf32_kernel<<<gg, 256>>>(Cb, Wo, bo, out, 0);
}